// round 1
// baseline (speedup 1.0000x reference)
#include <cuda_runtime.h>
#include <cuda_bf16.h>
#include <cstdint>

// ---------------- problem constants ----------------
#define DMODEL 2048
#define DSTATE 16
#define KER    4
#define DTRANK 128            // DMODEL/16
#define BSZ    2
#define SEQ    1024
#define MROWS  (BSZ*SEQ)      // 2048
#define XDBL_W (DTRANK + 2*DSTATE)  // 160

// ---------------- scratch (static device memory; no allocations allowed) ----
__device__ float g_xz  [(size_t)MROWS * (2*DMODEL)]; // 32 MB
__device__ float g_u   [(size_t)MROWS * DMODEL];     // 16 MB (post conv+silu)
__device__ float g_xdbl[(size_t)MROWS * XDBL_W];     // 1.25 MB
__device__ float g_dt  [(size_t)MROWS * DMODEL];     // 16 MB
__device__ float g_ypre[(size_t)MROWS * DMODEL];     // 16 MB

// ---------------- generic NT SGEMM: C[m,n] = sum_k A[m,k]*B[n,k] ------------
// A row-major [M,lda], B row-major [N,ldb] (K contiguous in both).
// EPI==0: plain store. EPI==1: softplus(acc + bias[n]).
#define BM 128
#define BN 128
#define BK 8

template<int EPI>
__global__ void __launch_bounds__(256)
sgemm_nt(const float* __restrict__ A, int lda,
         const float* __restrict__ B, int ldb,
         float* __restrict__ C, int ldc,
         int M, int N, int K,
         const float* __restrict__ bias)
{
    __shared__ float As[BK][BM];
    __shared__ float Bs[BK][BN];

    const int tid = threadIdx.x;
    const int m0 = blockIdx.y * BM;
    const int n0 = blockIdx.x * BN;

    const int arow = tid >> 1;        // 0..127
    const int acol = (tid & 1) * 4;   // 0 or 4

    const int tx = tid & 15;          // n sub-tile
    const int ty = tid >> 4;          // m sub-tile

    float acc[8][8];
#pragma unroll
    for (int i = 0; i < 8; i++)
#pragma unroll
        for (int j = 0; j < 8; j++) acc[i][j] = 0.f;

    for (int k0 = 0; k0 < K; k0 += BK) {
        float4 av = make_float4(0.f,0.f,0.f,0.f);
        float4 bv = make_float4(0.f,0.f,0.f,0.f);
        {
            int m = m0 + arow;
            if (m < M) av = *(const float4*)&A[(size_t)m * lda + k0 + acol];
            int n = n0 + arow;
            if (n < N) bv = *(const float4*)&B[(size_t)n * ldb + k0 + acol];
        }
        __syncthreads();
        As[acol+0][arow] = av.x; As[acol+1][arow] = av.y;
        As[acol+2][arow] = av.z; As[acol+3][arow] = av.w;
        Bs[acol+0][arow] = bv.x; Bs[acol+1][arow] = bv.y;
        Bs[acol+2][arow] = bv.z; Bs[acol+3][arow] = bv.w;
        __syncthreads();

#pragma unroll
        for (int kk = 0; kk < BK; kk++) {
            float af[8], bf[8];
            *(float4*)&af[0] = *(const float4*)&As[kk][ty*8];
            *(float4*)&af[4] = *(const float4*)&As[kk][ty*8+4];
            *(float4*)&bf[0] = *(const float4*)&Bs[kk][tx*8];
            *(float4*)&bf[4] = *(const float4*)&Bs[kk][tx*8+4];
#pragma unroll
            for (int i = 0; i < 8; i++)
#pragma unroll
                for (int j = 0; j < 8; j++)
                    acc[i][j] += af[i] * bf[j];
        }
    }

#pragma unroll
    for (int i = 0; i < 8; i++) {
        int m = m0 + ty*8 + i;
        if (m >= M) continue;
#pragma unroll
        for (int j = 0; j < 8; j++) {
            int n = n0 + tx*8 + j;
            if (n >= N) continue;
            float v = acc[i][j];
            if (EPI == 1) {
                v += bias[n];
                v = (v > 20.f) ? v : log1pf(expf(v));  // softplus
            }
            C[(size_t)m * ldc + n] = v;
        }
    }
}

// ---------------- depthwise causal conv (K=4) + SiLU ------------------------
__global__ void __launch_bounds__(256)
conv_silu_kernel(const float* __restrict__ xz,   // [MROWS, 2*DMODEL]
                 const float* __restrict__ conv_w, // [DMODEL, 4]
                 const float* __restrict__ conv_b, // [DMODEL]
                 float* __restrict__ u)            // [MROWS, DMODEL]
{
    int idx = blockIdx.x * blockDim.x + threadIdx.x;
    if (idx >= MROWS * DMODEL) return;
    int d = idx & (DMODEL - 1);
    int m = idx >> 11;            // / DMODEL
    int l = m & (SEQ - 1);
    int b = m >> 10;

    float w0 = conv_w[d*4+0], w1 = conv_w[d*4+1],
          w2 = conv_w[d*4+2], w3 = conv_w[d*4+3];
    float acc = conv_b[d];
    // conv[l] = b + sum_k w[k] * u_in[l - 3 + k]
    size_t base = (size_t)(b * SEQ) * (2*DMODEL) + d;
    if (l >= 3) acc += w0 * xz[base + (size_t)(l-3) * (2*DMODEL)];
    if (l >= 2) acc += w1 * xz[base + (size_t)(l-2) * (2*DMODEL)];
    if (l >= 1) acc += w2 * xz[base + (size_t)(l-1) * (2*DMODEL)];
    acc += w3 * xz[base + (size_t)l * (2*DMODEL)];

    float sig = 1.f / (1.f + expf(-acc));
    u[idx] = acc * sig;
}

// ---------------- selective scan + fused gate epilogue ----------------------
// Block: 256 threads = 16 d-channels x 16 states. Grid: BSZ * (DMODEL/16).
// h kept in registers; dt/u/B/C/z staged in smem in 64-step chunks.
#define DG 16
#define CL 64

__global__ void __launch_bounds__(256)
scan_kernel(const float* __restrict__ xdbl,   // [MROWS, 160]
            const float* __restrict__ dt,     // [MROWS, DMODEL]
            const float* __restrict__ u,      // [MROWS, DMODEL]
            const float* __restrict__ xz,     // [MROWS, 2*DMODEL] (z in 2nd half)
            const float* __restrict__ A_log,  // [DMODEL, 16]
            const float* __restrict__ Dskip,  // [DMODEL]
            float* __restrict__ ypre)         // [MROWS, DMODEL]
{
    const int b    = blockIdx.x >> 7;       // DMODEL/DG = 128 blocks per batch
    const int dblk = blockIdx.x & 127;
    const int d0   = dblk * DG;
    const int tid  = threadIdx.x;
    const int dloc = tid >> 4;
    const int n    = tid & 15;
    const int d    = d0 + dloc;

    const float Adn = -expf(A_log[d * DSTATE + n]);
    const float Dsk = Dskip[d];
    float h = 0.f;

    __shared__ float sdt[CL*DG], su[CL*DG], sz[CL*DG];
    __shared__ float sB[CL*DSTATE], sC[CL*DSTATE];

    for (int c = 0; c < SEQ / CL; c++) {
        const int l0 = c * CL;
        __syncthreads();
#pragma unroll
        for (int e = tid; e < CL*DG; e += 256) {
            int lr = e >> 4, el = e & 15;
            size_t row = (size_t)(b * SEQ + l0 + lr);
            sdt[e] = dt[row * DMODEL + d0 + el];
            su[e]  = u [row * DMODEL + d0 + el];
            sz[e]  = xz[row * (2*DMODEL) + DMODEL + d0 + el];
            sB[e]  = xdbl[row * XDBL_W + DTRANK + el];
            sC[e]  = xdbl[row * XDBL_W + DTRANK + DSTATE + el];
        }
        __syncthreads();

#pragma unroll 4
        for (int lr = 0; lr < CL; lr++) {
            float dtv = sdt[lr*16 + dloc];
            float uu  = su [lr*16 + dloc];
            float dA  = __expf(dtv * Adn);
            h = dA * h + (dtv * uu) * sB[lr*16 + n];
            float y = h * sC[lr*16 + n];
            y += __shfl_xor_sync(0xffffffffu, y, 8, 16);
            y += __shfl_xor_sync(0xffffffffu, y, 4, 16);
            y += __shfl_xor_sync(0xffffffffu, y, 2, 16);
            y += __shfl_xor_sync(0xffffffffu, y, 1, 16);
            if (n == 0) {
                float z   = sz[lr*16 + dloc];
                float sig = 1.f / (1.f + __expf(-z));
                ypre[(size_t)(b * SEQ + l0 + lr) * DMODEL + d] =
                    (y + uu * Dsk) * (z * sig);
            }
        }
    }
}

// ---------------- launch ----------------------------------------------------
extern "C" void kernel_launch(void* const* d_in, const int* in_sizes, int n_in,
                              void* d_out, int out_size)
{
    const float* x      = (const float*)d_in[0];
    const float* W_in   = (const float*)d_in[1];
    const float* conv_w = (const float*)d_in[2];
    const float* conv_b = (const float*)d_in[3];
    const float* W_xproj= (const float*)d_in[4];
    const float* W_dt   = (const float*)d_in[5];
    const float* b_dt   = (const float*)d_in[6];
    const float* A_log  = (const float*)d_in[7];
    const float* Dskip  = (const float*)d_in[8];
    const float* W_out  = (const float*)d_in[9];
    float* out = (float*)d_out;

    float *xz, *u, *xdbl, *dtb, *ypre;
    cudaGetSymbolAddress((void**)&xz,   g_xz);
    cudaGetSymbolAddress((void**)&u,    g_u);
    cudaGetSymbolAddress((void**)&xdbl, g_xdbl);
    cudaGetSymbolAddress((void**)&dtb,  g_dt);
    cudaGetSymbolAddress((void**)&ypre, g_ypre);

    // 1) xz = x @ W_in^T : [2048,2048] x [4096,2048]^T -> [2048,4096]
    {
        dim3 grid((2*DMODEL + BN - 1)/BN, (MROWS + BM - 1)/BM);
        sgemm_nt<0><<<grid, 256>>>(x, DMODEL, W_in, DMODEL, xz, 2*DMODEL,
                                   MROWS, 2*DMODEL, DMODEL, nullptr);
    }
    // 2) u = silu(causal_conv(xz[:, :2048]))
    {
        int total = MROWS * DMODEL;
        conv_silu_kernel<<<(total + 255)/256, 256>>>(xz, conv_w, conv_b, u);
    }
    // 3) x_dbl = u @ W_xproj^T : [2048,2048] x [160,2048]^T -> [2048,160]
    {
        dim3 grid((XDBL_W + BN - 1)/BN, (MROWS + BM - 1)/BM);
        sgemm_nt<0><<<grid, 256>>>(u, DMODEL, W_xproj, DMODEL, xdbl, XDBL_W,
                                   MROWS, XDBL_W, DMODEL, nullptr);
    }
    // 4) dt = softplus(x_dbl[:, :128] @ W_dt^T + b_dt) -> [2048,2048]
    {
        dim3 grid((DMODEL + BN - 1)/BN, (MROWS + BM - 1)/BM);
        sgemm_nt<1><<<grid, 256>>>(xdbl, XDBL_W, W_dt, DTRANK, dtb, DMODEL,
                                   MROWS, DMODEL, DTRANK, b_dt);
    }
    // 5) selective scan + (y + u*D) * silu(z)
    {
        scan_kernel<<<BSZ * (DMODEL/DG), 256>>>(xdbl, dtb, u, xz,
                                                A_log, Dskip, ypre);
    }
    // 6) out = ypre @ W_out^T : [2048,2048] x [2048,2048]^T -> [2048,2048]
    {
        dim3 grid((DMODEL + BN - 1)/BN, (MROWS + BM - 1)/BM);
        sgemm_nt<0><<<grid, 256>>>(ypre, DMODEL, W_out, DMODEL, out, DMODEL,
                                   MROWS, DMODEL, DMODEL, nullptr);
    }
}

// round 3
// speedup vs baseline: 2.6082x; 2.6082x over previous
#include <cuda_runtime.h>
#include <cuda_bf16.h>
#include <cstdint>

// ---------------- problem constants ----------------
#define DMODEL 2048
#define DSTATE 16
#define DTRANK 128
#define BSZ    2
#define SEQ    1024
#define MROWS  (BSZ*SEQ)            // 2048
#define XDBL_W (DTRANK + 2*DSTATE)  // 160
#define K3     (3*DMODEL)           // 6144
#define K3DT   (3*DTRANK)           // 384

// ---------------- static scratch ----------------
__device__ float g_xz  [(size_t)MROWS * (2*DMODEL)];
__device__ float g_u   [(size_t)MROWS * DMODEL];
__device__ float g_xdbl[(size_t)MROWS * XDBL_W];
__device__ float g_dt  [(size_t)MROWS * DMODEL];
__device__ float g_ypre[(size_t)MROWS * DMODEL];

__device__ __nv_bfloat16 g_xh3 [(size_t)MROWS  * K3];
__device__ __nv_bfloat16 g_wih3[(size_t)(2*DMODEL) * K3];
__device__ __nv_bfloat16 g_uh3 [(size_t)MROWS  * K3];
__device__ __nv_bfloat16 g_wxh3[(size_t)XDBL_W * K3];
__device__ __nv_bfloat16 g_dta3[(size_t)MROWS  * K3DT];
__device__ __nv_bfloat16 g_wdt3[(size_t)DMODEL * K3DT];
__device__ __nv_bfloat16 g_yph3[(size_t)MROWS  * K3];
__device__ __nv_bfloat16 g_woh3[(size_t)DMODEL * K3];

// ---------------- PTX helpers (all plain sm_90-level, no 'a' features) -----
__device__ __forceinline__ uint32_t smem_u32(const void* p) {
    uint32_t a;
    asm("{ .reg .u64 t; cvta.to.shared.u64 t, %1; cvt.u32.u64 %0, t; }" : "=r"(a) : "l"(p));
    return a;
}
__device__ __forceinline__ void cp_async16(uint32_t saddr, const void* gaddr, int src_bytes) {
    asm volatile("cp.async.cg.shared.global [%0], [%1], 16, %2;"
                 :: "r"(saddr), "l"(gaddr), "r"(src_bytes) : "memory");
}
#define CP_COMMIT() asm volatile("cp.async.commit_group;" ::: "memory")
#define CP_WAIT1()  asm volatile("cp.async.wait_group 1;" ::: "memory")

__device__ __forceinline__ void ldsm_x4(uint32_t* r, uint32_t addr) {
    asm volatile("ldmatrix.sync.aligned.m8n8.x4.shared.b16 {%0,%1,%2,%3}, [%4];"
                 : "=r"(r[0]), "=r"(r[1]), "=r"(r[2]), "=r"(r[3]) : "r"(addr));
}
__device__ __forceinline__ void mma16816(float* d, const uint32_t* a, const uint32_t* b) {
    asm volatile(
        "mma.sync.aligned.m16n8k16.row.col.f32.bf16.bf16.f32 "
        "{%0,%1,%2,%3}, {%4,%5,%6,%7}, {%8,%9}, {%0,%1,%2,%3};"
        : "+f"(d[0]), "+f"(d[1]), "+f"(d[2]), "+f"(d[3])
        : "r"(a[0]), "r"(a[1]), "r"(a[2]), "r"(a[3]), "r"(b[0]), "r"(b[1]));
}

// ---------------- bf16x3 split kernels ----------------
template<int ASIDE>
__global__ void __launch_bounds__(256)
split3_kernel(const float* __restrict__ src, int ld, int cols,
              __nv_bfloat16* __restrict__ dst, int total)
{
    int idx = blockIdx.x * blockDim.x + threadIdx.x;
    if (idx >= total) return;
    int halfc = cols >> 1;
    int r = idx / halfc;
    int c = idx - r * halfc;
    float v0 = src[(size_t)r * ld + 2*c];
    float v1 = src[(size_t)r * ld + 2*c + 1];
    __nv_bfloat16 h0 = __float2bfloat16(v0);
    __nv_bfloat16 l0 = __float2bfloat16(v0 - __bfloat162float(h0));
    __nv_bfloat16 h1 = __float2bfloat16(v1);
    __nv_bfloat16 l1 = __float2bfloat16(v1 - __bfloat162float(h1));
    __nv_bfloat162* out = (__nv_bfloat162*)(dst + (size_t)r * 3 * cols + 6*c);
    __nv_bfloat162 w0, w1, w2;
    if (ASIDE) { w0.x=h0; w0.y=h0; w1.x=l0; w1.y=h1; w2.x=h1; w2.y=l1; }
    else       { w0.x=h0; w0.y=l0; w1.x=h0; w1.y=h1; w2.x=l1; w2.y=h1; }
    out[0] = w0; out[1] = w1; out[2] = w2;
}

// ---------------- bf16 tensor-core GEMM (mma.sync path) --------------------
// C[m,n] = sum_k A[m,k]*B[n,k];  A:[M,K2], B:[N,K2] bf16 K-major.
// 128x128 tile, BK=64, 8 warps (each 64x32), double-buffered cp.async,
// SW128 swizzle in smem (conflict-free ldmatrix).
// EPI==1: softplus(acc + bias[n]).
#define GSMEM (2*32768)

template<int EPI>
__global__ void __launch_bounds__(256)
gemm_mma(const __nv_bfloat16* __restrict__ A,
         const __nv_bfloat16* __restrict__ B,
         float* __restrict__ C, int ldc,
         int N, int K2,
         const float* __restrict__ bias)
{
    extern __shared__ __align__(1024) char smem[];
    const uint32_t sbase = smem_u32(smem);

    const int tid  = threadIdx.x;
    const int wid  = tid >> 5;
    const int lane = tid & 31;
    const int m0 = blockIdx.y << 7;
    const int n0 = blockIdx.x << 7;
    const int wm = (wid & 1) * 64;   // warp m offset in tile
    const int wn = (wid >> 1) * 32;  // warp n offset in tile

    const int nch = K2 >> 6;

    // --- global->smem load lambda (one stage = A 16KB + B 16KB) ---
    // chunk id: A: 1024 chunks (128 rows x 8), B: same.
    const int lrow = tid >> 3;        // 0..31 base row step (x4 iters of 32 rows)
    const int lch  = tid & 7;         // 16B chunk within row
    auto load_stage = [&](int s, int i) {
        const int k0 = i << 6;
        const uint32_t sA = sbase + s * 32768;
        const uint32_t sB = sA + 16384;
#pragma unroll
        for (int j = 0; j < 4; j++) {
            int row = lrow + j * 32;
            uint32_t so = (uint32_t)(row * 128 + ((lch ^ (row & 7)) << 4));
            cp_async16(sA + so, A + (size_t)(m0 + row) * K2 + k0 + lch * 8, 16);
            int n = n0 + row;
            cp_async16(sB + so, B + (size_t)n * K2 + k0 + lch * 8, (n < N) ? 16 : 0);
        }
    };

    float acc[4][4][4];
#pragma unroll
    for (int i = 0; i < 4; i++)
#pragma unroll
        for (int j = 0; j < 4; j++)
#pragma unroll
            for (int e = 0; e < 4; e++) acc[i][j][e] = 0.f;

    // per-lane ldmatrix address components
    const int a_r = lane & 15;        // row within 16
    const int a_c = lane >> 4;        // 0/1 -> k-chunk half
    const int b_r = ((lane >> 4) & 1) * 8 + (lane & 7);
    const int b_c = (lane >> 3) & 1;

    load_stage(0, 0);
    CP_COMMIT();

    for (int i = 0; i < nch; i++) {
        if (i + 1 < nch) load_stage((i + 1) & 1, i + 1);
        CP_COMMIT();
        CP_WAIT1();
        __syncthreads();

        const uint32_t sA = sbase + (i & 1) * 32768;
        const uint32_t sB = sA + 16384;
#pragma unroll
        for (int ks = 0; ks < 4; ks++) {
            uint32_t af[4][4], bf[2][4];
#pragma unroll
            for (int mi = 0; mi < 4; mi++) {
                int row = wm + mi * 16 + a_r;
                int ch  = ks * 2 + a_c;
                ldsm_x4(af[mi], sA + row * 128 + ((ch ^ (row & 7)) << 4));
            }
#pragma unroll
            for (int nj = 0; nj < 2; nj++) {
                int row = wn + nj * 16 + b_r;
                int ch  = ks * 2 + b_c;
                ldsm_x4(bf[nj], sB + row * 128 + ((ch ^ (row & 7)) << 4));
            }
#pragma unroll
            for (int mi = 0; mi < 4; mi++)
#pragma unroll
                for (int ni = 0; ni < 4; ni++)
                    mma16816(acc[mi][ni], af[mi], &bf[ni >> 1][(ni & 1) * 2]);
        }
        __syncthreads();
    }

    // --- epilogue ---
    const int er = lane >> 2;         // row 0..7
    const int ec = (lane & 3) * 2;    // col pair
#pragma unroll
    for (int mi = 0; mi < 4; mi++) {
#pragma unroll
        for (int half = 0; half < 2; half++) {
            int m = m0 + wm + mi * 16 + er + half * 8;
            float* crow = C + (size_t)m * ldc;
#pragma unroll
            for (int ni = 0; ni < 4; ni++) {
                int n = n0 + wn + ni * 8 + ec;
                if (n >= N) continue;
                float v0 = acc[mi][ni][half * 2 + 0];
                float v1 = acc[mi][ni][half * 2 + 1];
                if (EPI == 1) {
                    v0 += bias[n];     v1 += bias[n + 1];
                    v0 = (v0 > 20.f) ? v0 : log1pf(expf(v0));
                    v1 = (v1 > 20.f) ? v1 : log1pf(expf(v1));
                }
                *(float2*)&crow[n] = make_float2(v0, v1);
            }
        }
    }
}

// ---------------- depthwise causal conv (K=4) + SiLU ----------------
__global__ void __launch_bounds__(256)
conv_silu_kernel(const float* __restrict__ xz,
                 const float* __restrict__ conv_w,
                 const float* __restrict__ conv_b,
                 float* __restrict__ u)
{
    int idx = blockIdx.x * blockDim.x + threadIdx.x;
    if (idx >= MROWS * DMODEL) return;
    int d = idx & (DMODEL - 1);
    int m = idx >> 11;
    int l = m & (SEQ - 1);
    int b = m >> 10;

    float w0 = conv_w[d*4+0], w1 = conv_w[d*4+1],
          w2 = conv_w[d*4+2], w3 = conv_w[d*4+3];
    float acc = conv_b[d];
    size_t base = (size_t)(b * SEQ) * (2*DMODEL) + d;
    if (l >= 3) acc += w0 * xz[base + (size_t)(l-3) * (2*DMODEL)];
    if (l >= 2) acc += w1 * xz[base + (size_t)(l-2) * (2*DMODEL)];
    if (l >= 1) acc += w2 * xz[base + (size_t)(l-1) * (2*DMODEL)];
    acc += w3 * xz[base + (size_t)l * (2*DMODEL)];
    float sig = 1.f / (1.f + expf(-acc));
    u[idx] = acc * sig;
}

// ---------------- selective scan + fused gate ----------------
#define DG 16
#define CL 64
__global__ void __launch_bounds__(256)
scan_kernel(const float* __restrict__ xdbl,
            const float* __restrict__ dt,
            const float* __restrict__ u,
            const float* __restrict__ xz,
            const float* __restrict__ A_log,
            const float* __restrict__ Dskip,
            float* __restrict__ ypre)
{
    const int b    = blockIdx.x >> 7;
    const int dblk = blockIdx.x & 127;
    const int d0   = dblk * DG;
    const int tid  = threadIdx.x;
    const int dloc = tid >> 4;
    const int n    = tid & 15;
    const int d    = d0 + dloc;

    const float Adn = -expf(A_log[d * DSTATE + n]);
    const float Dsk = Dskip[d];
    float h = 0.f;

    __shared__ float sdt[CL*DG], su[CL*DG], sz[CL*DG];
    __shared__ float sB[CL*DSTATE], sC[CL*DSTATE];

    for (int c = 0; c < SEQ / CL; c++) {
        const int l0 = c * CL;
        __syncthreads();
#pragma unroll
        for (int e = tid; e < CL*DG; e += 256) {
            int lr = e >> 4, el = e & 15;
            size_t row = (size_t)(b * SEQ + l0 + lr);
            sdt[e] = dt[row * DMODEL + d0 + el];
            su[e]  = u [row * DMODEL + d0 + el];
            sz[e]  = xz[row * (2*DMODEL) + DMODEL + d0 + el];
            sB[e]  = xdbl[row * XDBL_W + DTRANK + el];
            sC[e]  = xdbl[row * XDBL_W + DTRANK + DSTATE + el];
        }
        __syncthreads();

#pragma unroll 4
        for (int lr = 0; lr < CL; lr++) {
            float dtv = sdt[lr*16 + dloc];
            float uu  = su [lr*16 + dloc];
            float dA  = __expf(dtv * Adn);
            h = dA * h + (dtv * uu) * sB[lr*16 + n];
            float y = h * sC[lr*16 + n];
            y += __shfl_xor_sync(0xffffffffu, y, 8, 16);
            y += __shfl_xor_sync(0xffffffffu, y, 4, 16);
            y += __shfl_xor_sync(0xffffffffu, y, 2, 16);
            y += __shfl_xor_sync(0xffffffffu, y, 1, 16);
            if (n == 0) {
                float z   = sz[lr*16 + dloc];
                float sig = 1.f / (1.f + __expf(-z));
                ypre[(size_t)(b * SEQ + l0 + lr) * DMODEL + d] =
                    (y + uu * Dsk) * (z * sig);
            }
        }
    }
}

// ---------------- launch ----------------
extern "C" void kernel_launch(void* const* d_in, const int* in_sizes, int n_in,
                              void* d_out, int out_size)
{
    const float* x      = (const float*)d_in[0];
    const float* W_in   = (const float*)d_in[1];
    const float* conv_w = (const float*)d_in[2];
    const float* conv_b = (const float*)d_in[3];
    const float* W_xproj= (const float*)d_in[4];
    const float* W_dt   = (const float*)d_in[5];
    const float* b_dt   = (const float*)d_in[6];
    const float* A_log  = (const float*)d_in[7];
    const float* Dskip  = (const float*)d_in[8];
    const float* W_out  = (const float*)d_in[9];
    float* out = (float*)d_out;

    float *xz, *u, *xdbl, *dtb, *ypre;
    __nv_bfloat16 *xh3, *wih3, *uh3, *wxh3, *dta3, *wdt3, *yph3, *woh3;
    cudaGetSymbolAddress((void**)&xz,   g_xz);
    cudaGetSymbolAddress((void**)&u,    g_u);
    cudaGetSymbolAddress((void**)&xdbl, g_xdbl);
    cudaGetSymbolAddress((void**)&dtb,  g_dt);
    cudaGetSymbolAddress((void**)&ypre, g_ypre);
    cudaGetSymbolAddress((void**)&xh3,  g_xh3);
    cudaGetSymbolAddress((void**)&wih3, g_wih3);
    cudaGetSymbolAddress((void**)&uh3,  g_uh3);
    cudaGetSymbolAddress((void**)&wxh3, g_wxh3);
    cudaGetSymbolAddress((void**)&dta3, g_dta3);
    cudaGetSymbolAddress((void**)&wdt3, g_wdt3);
    cudaGetSymbolAddress((void**)&yph3, g_yph3);
    cudaGetSymbolAddress((void**)&woh3, g_woh3);

    static int attr_set = 0;
    cudaFuncSetAttribute(gemm_mma<0>, cudaFuncAttributeMaxDynamicSharedMemorySize, GSMEM);
    cudaFuncSetAttribute(gemm_mma<1>, cudaFuncAttributeMaxDynamicSharedMemorySize, GSMEM);
    (void)attr_set;

    // --- 1) split x, W_in; xz = x @ W_in^T ---
    {
        int tot = MROWS * DMODEL / 2;
        split3_kernel<1><<<(tot+255)/256, 256>>>(x, DMODEL, DMODEL, xh3, tot);
        int totw = (2*DMODEL) * DMODEL / 2;
        split3_kernel<0><<<(totw+255)/256, 256>>>(W_in, DMODEL, DMODEL, wih3, totw);
        dim3 grid((2*DMODEL)/128, MROWS/128);
        gemm_mma<0><<<grid, 256, GSMEM>>>(xh3, wih3, xz, 2*DMODEL,
                                          2*DMODEL, K3, nullptr);
    }
    // --- 2) u = silu(conv(xz[:, :2048])) ---
    {
        int total = MROWS * DMODEL;
        conv_silu_kernel<<<(total+255)/256, 256>>>(xz, conv_w, conv_b, u);
    }
    // --- 3) x_dbl = u @ W_xproj^T ---
    {
        int tot = MROWS * DMODEL / 2;
        split3_kernel<1><<<(tot+255)/256, 256>>>(u, DMODEL, DMODEL, uh3, tot);
        int totw = XDBL_W * DMODEL / 2;
        split3_kernel<0><<<(totw+255)/256, 256>>>(W_xproj, DMODEL, DMODEL, wxh3, totw);
        dim3 grid((XDBL_W + 127)/128, MROWS/128);
        gemm_mma<0><<<grid, 256, GSMEM>>>(uh3, wxh3, xdbl, XDBL_W,
                                          XDBL_W, K3, nullptr);
    }
    // --- 4) dt = softplus(x_dbl[:, :128] @ W_dt^T + b_dt) ---
    {
        int tot = MROWS * DTRANK / 2;
        split3_kernel<1><<<(tot+255)/256, 256>>>(xdbl, XDBL_W, DTRANK, dta3, tot);
        int totw = DMODEL * DTRANK / 2;
        split3_kernel<0><<<(totw+255)/256, 256>>>(W_dt, DTRANK, DTRANK, wdt3, totw);
        dim3 grid(DMODEL/128, MROWS/128);
        gemm_mma<1><<<grid, 256, GSMEM>>>(dta3, wdt3, dtb, DMODEL,
                                          DMODEL, K3DT, b_dt);
    }
    // --- 5) selective scan + gate ---
    scan_kernel<<<BSZ * (DMODEL/DG), 256>>>(xdbl, dtb, u, xz, A_log, Dskip, ypre);
    // --- 6) out = ypre @ W_out^T ---
    {
        int tot = MROWS * DMODEL / 2;
        split3_kernel<1><<<(tot+255)/256, 256>>>(ypre, DMODEL, DMODEL, yph3, tot);
        int totw = DMODEL * DMODEL / 2;
        split3_kernel<0><<<(totw+255)/256, 256>>>(W_out, DMODEL, DMODEL, woh3, totw);
        dim3 grid(DMODEL/128, MROWS/128);
        gemm_mma<0><<<grid, 256, GSMEM>>>(yph3, woh3, out, DMODEL,
                                          DMODEL, K3, nullptr);
    }
}